// round 3
// baseline (speedup 1.0000x reference)
#include <cuda_runtime.h>
#include <math.h>
#include <stdint.h>

// Problem constants (fixed by the dataset)
#define N_NODES   100000
#define N_EDGES   1600000
#define HIDDEN    128
#define NUM_RBF   64
#define NF        128          // NUM_FILTERS
#define CUTOFF    5.0f
#define PI_F      3.14159265358979323846f

// ---------------------------------------------------------------------------
// Scratch (no allocations allowed -> __device__ globals)
// ---------------------------------------------------------------------------
__device__ __align__(16) float g_xf [N_NODES * NF];   // x @ lin1_w
__device__ __align__(16) float g_agg[N_NODES * NF];   // scatter accumulator
__device__ float g_cnt[N_NODES];                      // in-degree counts

__device__ __forceinline__ float silu_f(float v) {
    return v / (1.0f + __expf(-v));
}

__device__ __forceinline__ int clamp_idx(int v) {
    v = v < 0 ? 0 : v;
    return v >= N_NODES ? N_NODES - 1 : v;
}

// ---------------------------------------------------------------------------
// Kernel 1: zero agg + cnt
// ---------------------------------------------------------------------------
__global__ void zero_kernel() {
    int idx = blockIdx.x * blockDim.x + threadIdx.x;
    int stride = gridDim.x * blockDim.x;
    float4* agg4 = reinterpret_cast<float4*>(g_agg);
    const int n4 = N_NODES * (NF / 4);
    float4 z = make_float4(0.f, 0.f, 0.f, 0.f);
    for (int i = idx; i < n4; i += stride) agg4[i] = z;
    for (int i = idx; i < N_NODES; i += stride) g_cnt[i] = 0.f;
}

// ---------------------------------------------------------------------------
// Kernel 2: in-degree counts (scatter count over dst)  [edge_index is int32]
// ---------------------------------------------------------------------------
__global__ void cnt_kernel(const int* __restrict__ edge_index) {
    int idx = blockIdx.x * blockDim.x + threadIdx.x;
    int stride = gridDim.x * blockDim.x;
    for (int e = idx; e < N_EDGES; e += stride) {
        int d = clamp_idx(edge_index[N_EDGES + e]);
        atomicAdd(&g_cnt[d], 1.0f);
    }
}

// ---------------------------------------------------------------------------
// Kernel 3: xf = x @ lin1_w    [100k,128]@[128,128]
// 256 threads, TILE_N=32 nodes/tile, weights in smem, 4x4 register tile
// ---------------------------------------------------------------------------
__global__ void xf_kernel(const float* __restrict__ x,
                          const float* __restrict__ lin1_w) {
    extern __shared__ float sm[];
    float* ws = sm;            // 128*128
    float* xs = ws + 16384;    // 32*128

    const int tid = threadIdx.x;
    for (int i = tid; i < 16384 / 4; i += 256)
        reinterpret_cast<float4*>(ws)[i] =
            reinterpret_cast<const float4*>(lin1_w)[i];
    __syncthreads();

    const int j0 = (tid & 31) * 4;     // feature group
    const int n0 = (tid >> 5) * 4;     // node group within tile (8 groups * 4)

    const int n_tiles = N_NODES / 32;  // 3125 exact
    for (int t = blockIdx.x; t < n_tiles; t += gridDim.x) {
        const int base = t * 32;
        for (int i = tid; i < 32 * 32; i += 256)   // float4 units
            reinterpret_cast<float4*>(xs)[i] =
                reinterpret_cast<const float4*>(x + base * HIDDEN)[i];
        __syncthreads();

        float4 acc[4];
        #pragma unroll
        for (int i = 0; i < 4; i++) acc[i] = make_float4(0.f, 0.f, 0.f, 0.f);

        #pragma unroll 8
        for (int k = 0; k < HIDDEN; k++) {
            float4 w4 = *reinterpret_cast<const float4*>(&ws[k * NF + j0]);
            #pragma unroll
            for (int i = 0; i < 4; i++) {
                float a = xs[(n0 + i) * HIDDEN + k];
                acc[i].x += a * w4.x; acc[i].y += a * w4.y;
                acc[i].z += a * w4.z; acc[i].w += a * w4.w;
            }
        }
        #pragma unroll
        for (int i = 0; i < 4; i++)
            *reinterpret_cast<float4*>(&g_xf[(base + n0 + i) * NF + j0]) = acc[i];
        __syncthreads();
    }
}

// ---------------------------------------------------------------------------
// Kernel 4: fused edge kernel
//   C = cosine cutoff; h = silu(attr@W1+b1); W = (h@W2+b2)*C;
//   msg = xf[src]*W; scalar REDG.ADD -> agg[dst]
// 512 threads, TILE_E=64 edges/tile, both weight mats in smem
// ---------------------------------------------------------------------------
#define TILE_E 64
__global__ void edge_kernel(const int* __restrict__ edge_index,
                            const float* __restrict__ edge_weight,
                            const float* __restrict__ edge_attr,
                            const float* __restrict__ mlp_w1,
                            const float* __restrict__ mlp_b1,
                            const float* __restrict__ mlp_w2,
                            const float* __restrict__ mlp_b2) {
    extern __shared__ float sm[];
    float* W1s    = sm;               // 64*128
    float* W2s    = W1s + 8192;       // 128*128
    float* b1s    = W2s + 16384;      // 128
    float* b2s    = b1s + 128;        // 128
    float* attr_s = b2s + 128;        // 64*64
    float* h_s    = attr_s + 4096;    // 64*128
    float* Cs     = h_s + 8192;       // 64
    int*   srcs   = (int*)(Cs + 64);  // 64
    int*   dsts   = srcs + 64;        // 64

    const int tid = threadIdx.x;

    // preload weights + biases (once per block)
    for (int i = tid; i < 8192 / 4; i += 512)
        reinterpret_cast<float4*>(W1s)[i] =
            reinterpret_cast<const float4*>(mlp_w1)[i];
    for (int i = tid; i < 16384 / 4; i += 512)
        reinterpret_cast<float4*>(W2s)[i] =
            reinterpret_cast<const float4*>(mlp_w2)[i];
    if (tid < 128) { b1s[tid] = mlp_b1[tid]; b2s[tid] = mlp_b2[tid]; }
    __syncthreads();

    const int j0 = (tid & 31) * 4;   // feature group (warp lanes cover 128 feats)
    const int e0 = (tid >> 5) * 4;   // edge group (16 groups * 4 = 64)

    const int n_tiles = N_EDGES / TILE_E;   // 25000 exact
    for (int t = blockIdx.x; t < n_tiles; t += gridDim.x) {
        const int base = t * TILE_E;

        if (tid < TILE_E) {
            int e = base + tid;
            srcs[tid] = clamp_idx(edge_index[e]);
            dsts[tid] = clamp_idx(edge_index[N_EDGES + e]);
            float w = edge_weight[e];
            float c = 0.5f * (__cosf(w * (PI_F / CUTOFF)) + 1.0f);
            Cs[tid] = (w < CUTOFF) ? c : 0.0f;
        }
        for (int i = tid; i < TILE_E * NUM_RBF / 4; i += 512)
            reinterpret_cast<float4*>(attr_s)[i] =
                reinterpret_cast<const float4*>(edge_attr + base * NUM_RBF)[i];
        __syncthreads();

        // ---- phase 1: h = silu(attr @ W1 + b1) ----
        float4 acc[4];
        #pragma unroll
        for (int i = 0; i < 4; i++) acc[i] = make_float4(0.f, 0.f, 0.f, 0.f);
        #pragma unroll 8
        for (int k = 0; k < NUM_RBF; k++) {
            float4 w4 = *reinterpret_cast<const float4*>(&W1s[k * NF + j0]);
            #pragma unroll
            for (int i = 0; i < 4; i++) {
                float a = attr_s[(e0 + i) * NUM_RBF + k];
                acc[i].x += a * w4.x; acc[i].y += a * w4.y;
                acc[i].z += a * w4.z; acc[i].w += a * w4.w;
            }
        }
        {
            float4 bv = *reinterpret_cast<const float4*>(&b1s[j0]);
            #pragma unroll
            for (int i = 0; i < 4; i++) {
                float4 h4;
                h4.x = silu_f(acc[i].x + bv.x);
                h4.y = silu_f(acc[i].y + bv.y);
                h4.z = silu_f(acc[i].z + bv.z);
                h4.w = silu_f(acc[i].w + bv.w);
                *reinterpret_cast<float4*>(&h_s[(e0 + i) * NF + j0]) = h4;
            }
        }
        __syncthreads();

        // ---- phase 2: W = (h @ W2 + b2) * C ; gather/scale/scatter ----
        #pragma unroll
        for (int i = 0; i < 4; i++) acc[i] = make_float4(0.f, 0.f, 0.f, 0.f);
        #pragma unroll 8
        for (int k = 0; k < NF; k++) {
            float4 w4 = *reinterpret_cast<const float4*>(&W2s[k * NF + j0]);
            #pragma unroll
            for (int i = 0; i < 4; i++) {
                float a = h_s[(e0 + i) * NF + k];
                acc[i].x += a * w4.x; acc[i].y += a * w4.y;
                acc[i].z += a * w4.z; acc[i].w += a * w4.w;
            }
        }
        {
            float4 bv = *reinterpret_cast<const float4*>(&b2s[j0]);
            #pragma unroll
            for (int i = 0; i < 4; i++) {
                const int e = e0 + i;
                const float c = Cs[e];
                const int s = srcs[e];
                const int d = dsts[e];
                float4 xf4 = *reinterpret_cast<const float4*>(&g_xf[s * NF + j0]);
                float* dst = &g_agg[d * NF + j0];
                atomicAdd(dst + 0, (acc[i].x + bv.x) * c * xf4.x);
                atomicAdd(dst + 1, (acc[i].y + bv.y) * c * xf4.y);
                atomicAdd(dst + 2, (acc[i].z + bv.z) * c * xf4.z);
                atomicAdd(dst + 3, (acc[i].w + bv.w) * c * xf4.w);
            }
        }
        __syncthreads();   // protect attr_s/Cs/srcs/dsts for next tile
    }
}

// ---------------------------------------------------------------------------
// Kernel 5: node tail
//   agg /= max(cnt,1); o = silu(agg@lin2+b2); out = o@lin_w+lin_b
// ---------------------------------------------------------------------------
__global__ void node_kernel(const float* __restrict__ lin2_w,
                            const float* __restrict__ lin2_b,
                            const float* __restrict__ lin_w,
                            const float* __restrict__ lin_b,
                            float* __restrict__ out) {
    extern __shared__ float sm[];
    float* L2s = sm;             // 128*128 lin2_w
    float* Ls  = L2s + 16384;    // 128*128 lin_w
    float* b2s = Ls + 16384;     // 128
    float* bs  = b2s + 128;      // 128
    float* a_s = bs + 128;       // 64*128
    float* t_s = a_s + 8192;     // 64*128

    const int tid = threadIdx.x;
    for (int i = tid; i < 16384 / 4; i += 512) {
        reinterpret_cast<float4*>(L2s)[i] =
            reinterpret_cast<const float4*>(lin2_w)[i];
        reinterpret_cast<float4*>(Ls)[i] =
            reinterpret_cast<const float4*>(lin_w)[i];
    }
    if (tid < 128) { b2s[tid] = lin2_b[tid]; bs[tid] = lin_b[tid]; }
    __syncthreads();

    const int j0 = (tid & 31) * 4;
    const int n0 = (tid >> 5) * 4;   // 16 groups * 4 = 64 nodes

    const int n_tiles = (N_NODES + 63) / 64;   // 1563 (last tile: 32 nodes)
    for (int t = blockIdx.x; t < n_tiles; t += gridDim.x) {
        const int base = t * 64;

        // load + normalize agg tile
        for (int i = tid; i < 64 * 32; i += 512) {   // float4 units
            int r  = i >> 5;
            int cg = i & 31;
            int n  = base + r;
            float4 v = make_float4(0.f, 0.f, 0.f, 0.f);
            if (n < N_NODES) {
                v = *reinterpret_cast<const float4*>(&g_agg[n * NF + cg * 4]);
                float inv = 1.0f / fmaxf(g_cnt[n], 1.0f);
                v.x *= inv; v.y *= inv; v.z *= inv; v.w *= inv;
            }
            *reinterpret_cast<float4*>(&a_s[r * NF + cg * 4]) = v;
        }
        __syncthreads();

        // phase A: t = silu(a @ lin2 + b2)
        float4 acc[4];
        #pragma unroll
        for (int i = 0; i < 4; i++) acc[i] = make_float4(0.f, 0.f, 0.f, 0.f);
        #pragma unroll 8
        for (int k = 0; k < NF; k++) {
            float4 w4 = *reinterpret_cast<const float4*>(&L2s[k * HIDDEN + j0]);
            #pragma unroll
            for (int i = 0; i < 4; i++) {
                float a = a_s[(n0 + i) * NF + k];
                acc[i].x += a * w4.x; acc[i].y += a * w4.y;
                acc[i].z += a * w4.z; acc[i].w += a * w4.w;
            }
        }
        {
            float4 bv = *reinterpret_cast<const float4*>(&b2s[j0]);
            #pragma unroll
            for (int i = 0; i < 4; i++) {
                float4 h4;
                h4.x = silu_f(acc[i].x + bv.x);
                h4.y = silu_f(acc[i].y + bv.y);
                h4.z = silu_f(acc[i].z + bv.z);
                h4.w = silu_f(acc[i].w + bv.w);
                *reinterpret_cast<float4*>(&t_s[(n0 + i) * HIDDEN + j0]) = h4;
            }
        }
        __syncthreads();

        // phase B: out = t @ lin_w + lin_b
        #pragma unroll
        for (int i = 0; i < 4; i++) acc[i] = make_float4(0.f, 0.f, 0.f, 0.f);
        #pragma unroll 8
        for (int k = 0; k < HIDDEN; k++) {
            float4 w4 = *reinterpret_cast<const float4*>(&Ls[k * HIDDEN + j0]);
            #pragma unroll
            for (int i = 0; i < 4; i++) {
                float a = t_s[(n0 + i) * HIDDEN + k];
                acc[i].x += a * w4.x; acc[i].y += a * w4.y;
                acc[i].z += a * w4.z; acc[i].w += a * w4.w;
            }
        }
        {
            float4 bv = *reinterpret_cast<const float4*>(&bs[j0]);
            #pragma unroll
            for (int i = 0; i < 4; i++) {
                int n = base + n0 + i;
                if (n < N_NODES) {
                    float4 o;
                    o.x = acc[i].x + bv.x; o.y = acc[i].y + bv.y;
                    o.z = acc[i].z + bv.z; o.w = acc[i].w + bv.w;
                    *reinterpret_cast<float4*>(&out[n * HIDDEN + j0]) = o;
                }
            }
        }
        __syncthreads();
    }
}

// ---------------------------------------------------------------------------
// launch
// ---------------------------------------------------------------------------
extern "C" void kernel_launch(void* const* d_in, const int* in_sizes, int n_in,
                              void* d_out, int out_size) {
    const float* x   = (const float*)d_in[0];
    const int*   ei  = (const int*)d_in[1];      // int32! (JAX x64 disabled)
    const float* ew  = (const float*)d_in[2];
    const float* ea  = (const float*)d_in[3];
    const float* w1  = (const float*)d_in[4];
    const float* b1  = (const float*)d_in[5];
    const float* w2  = (const float*)d_in[6];
    const float* b2  = (const float*)d_in[7];
    const float* l1w = (const float*)d_in[8];
    const float* l2w = (const float*)d_in[9];
    const float* l2b = (const float*)d_in[10];
    const float* lw  = (const float*)d_in[11];
    const float* lb  = (const float*)d_in[12];
    float* out = (float*)d_out;

    const int smem_xf   = (16384 + 4096) * 4;
    const int smem_edge = 37312 * 4;
    const int smem_node = 49408 * 4;
    cudaFuncSetAttribute(xf_kernel,   cudaFuncAttributeMaxDynamicSharedMemorySize, smem_xf);
    cudaFuncSetAttribute(edge_kernel, cudaFuncAttributeMaxDynamicSharedMemorySize, smem_edge);
    cudaFuncSetAttribute(node_kernel, cudaFuncAttributeMaxDynamicSharedMemorySize, smem_node);

    zero_kernel<<<1024, 256>>>();
    cnt_kernel<<<2048, 256>>>(ei);
    xf_kernel<<<296, 256, smem_xf>>>(x, l1w);
    edge_kernel<<<148, 512, smem_edge>>>(ei, ew, ea, w1, b1, w2, b2);
    node_kernel<<<148, 512, smem_node>>>(l2w, l2b, lw, lb, out);
}

// round 5
// speedup vs baseline: 1.5633x; 1.5633x over previous
#include <cuda_runtime.h>
#include <math.h>
#include <stdint.h>

#define N_NODES   100000
#define N_EDGES   1600000
#define HIDDEN    128
#define NUM_RBF   64
#define NF        128
#define CUTOFF    5.0f
#define PI_F      3.14159265358979323846f

// ---------------------------------------------------------------------------
// Scratch
// ---------------------------------------------------------------------------
__device__ __align__(16) float g_xf [N_NODES * NF];
__device__ __align__(16) float g_agg[N_NODES * NF];
__device__ float g_cnt[N_NODES];

__device__ __forceinline__ float silu_f(float v) {
    return v / (1.0f + __expf(-v));
}

__device__ __forceinline__ int clamp_idx(int v) {
    v = v < 0 ? 0 : v;
    return v >= N_NODES ? N_NODES - 1 : v;
}

// ---- f32x2 packed-FMA helpers (Blackwell; FFMA2 only reachable via PTX) ----
__device__ __forceinline__ unsigned long long pack_rep2(float a) {
    unsigned long long r;
    asm("mov.b64 %0, {%1, %1};" : "=l"(r) : "f"(a));
    return r;
}
__device__ __forceinline__ void fma2(unsigned long long& d,
                                     unsigned long long a,
                                     unsigned long long b) {
    asm("fma.rn.f32x2 %0, %1, %2, %0;" : "+l"(d) : "l"(a), "l"(b));
}
__device__ __forceinline__ void unpack2(unsigned long long v, float& lo, float& hi) {
    asm("mov.b64 {%0, %1}, %2;" : "=f"(lo), "=f"(hi) : "l"(v));
}
// 16B shared load as two packed f32x2 (aligned)
__device__ __forceinline__ void lds_v2u64(const float* p,
                                          unsigned long long& w01,
                                          unsigned long long& w23) {
    uint32_t addr = (uint32_t)__cvta_generic_to_shared(p);
    asm("ld.shared.v2.u64 {%0, %1}, [%2];" : "=l"(w01), "=l"(w23) : "r"(addr));
}

// ---------------------------------------------------------------------------
// Kernel 1: zero agg + cnt
// ---------------------------------------------------------------------------
__global__ void zero_kernel() {
    int idx = blockIdx.x * blockDim.x + threadIdx.x;
    int stride = gridDim.x * blockDim.x;
    float4* agg4 = reinterpret_cast<float4*>(g_agg);
    const int n4 = N_NODES * (NF / 4);
    float4 z = make_float4(0.f, 0.f, 0.f, 0.f);
    for (int i = idx; i < n4; i += stride) agg4[i] = z;
    for (int i = idx; i < N_NODES; i += stride) g_cnt[i] = 0.f;
}

// ---------------------------------------------------------------------------
// Kernel 2: in-degree counts
// ---------------------------------------------------------------------------
__global__ void cnt_kernel(const int* __restrict__ edge_index) {
    int idx = blockIdx.x * blockDim.x + threadIdx.x;
    int stride = gridDim.x * blockDim.x;
    for (int e = idx; e < N_EDGES; e += stride) {
        int d = clamp_idx(edge_index[N_EDGES + e]);
        atomicAdd(&g_cnt[d], 1.0f);
    }
}

// ---------------------------------------------------------------------------
// Kernel 3: xf = x @ lin1_w
// ---------------------------------------------------------------------------
__global__ void xf_kernel(const float* __restrict__ x,
                          const float* __restrict__ lin1_w) {
    extern __shared__ float sm[];
    float* ws = sm;            // 128*128
    float* xs = ws + 16384;    // 32*128

    const int tid = threadIdx.x;
    for (int i = tid; i < 16384 / 4; i += 256)
        reinterpret_cast<float4*>(ws)[i] =
            reinterpret_cast<const float4*>(lin1_w)[i];
    __syncthreads();

    const int j0 = (tid & 31) * 4;
    const int n0 = (tid >> 5) * 4;

    const int n_tiles = N_NODES / 32;
    for (int t = blockIdx.x; t < n_tiles; t += gridDim.x) {
        const int base = t * 32;
        for (int i = tid; i < 32 * 32; i += 256)
            reinterpret_cast<float4*>(xs)[i] =
                reinterpret_cast<const float4*>(x + base * HIDDEN)[i];
        __syncthreads();

        float4 acc[4];
        #pragma unroll
        for (int i = 0; i < 4; i++) acc[i] = make_float4(0.f, 0.f, 0.f, 0.f);

        #pragma unroll 8
        for (int k = 0; k < HIDDEN; k++) {
            float4 w4 = *reinterpret_cast<const float4*>(&ws[k * NF + j0]);
            #pragma unroll
            for (int i = 0; i < 4; i++) {
                float a = xs[(n0 + i) * HIDDEN + k];
                acc[i].x += a * w4.x; acc[i].y += a * w4.y;
                acc[i].z += a * w4.z; acc[i].w += a * w4.w;
            }
        }
        #pragma unroll
        for (int i = 0; i < 4; i++)
            *reinterpret_cast<float4*>(&g_xf[(base + n0 + i) * NF + j0]) = acc[i];
        __syncthreads();
    }
}

// ---------------------------------------------------------------------------
// Kernel 4: fused edge kernel, f32x2 packed math, warp-autonomous (no BAR in loop)
// 512 threads = 16 warps; each warp owns 8 edges per tile iteration.
// Per-warp smem slices of attr (8x64) and h (8x128); weights shared read-only.
// ---------------------------------------------------------------------------
#define TILE_E 128   // 16 warps * 8 edges
__global__ __launch_bounds__(512, 1)
void edge_kernel(const int* __restrict__ edge_index,
                 const float* __restrict__ edge_weight,
                 const float* __restrict__ edge_attr,
                 const float* __restrict__ mlp_w1,
                 const float* __restrict__ mlp_b1,
                 const float* __restrict__ mlp_w2,
                 const float* __restrict__ mlp_b2) {
    extern __shared__ float sm[];
    float* W1s    = sm;                 // 64*128   =  8192
    float* W2s    = W1s + 8192;         // 128*128  = 16384
    float* b1s    = W2s + 16384;        // 128
    float* b2s    = b1s + 128;          // 128
    float* attr_s = b2s + 128;          // 128*64   =  8192
    float* h_s    = attr_s + 8192;      // 128*128  = 16384
    float* Cs     = h_s + 16384;        // 128
    int*   srcs   = (int*)(Cs + 128);   // 128
    int*   dsts   = srcs + 128;         // 128
    // total floats: 49792 -> 199168 B

    const int tid  = threadIdx.x;
    const int lane = tid & 31;
    const int wrp  = tid >> 5;          // 0..15
    const int e0   = wrp * 8;           // this warp's edge slice within tile

    // preload weights + biases (once)
    for (int i = tid; i < 8192 / 4; i += 512)
        reinterpret_cast<float4*>(W1s)[i] =
            reinterpret_cast<const float4*>(mlp_w1)[i];
    for (int i = tid; i < 16384 / 4; i += 512)
        reinterpret_cast<float4*>(W2s)[i] =
            reinterpret_cast<const float4*>(mlp_w2)[i];
    if (tid < 128) { b1s[tid] = mlp_b1[tid]; b2s[tid] = mlp_b2[tid]; }
    __syncthreads();

    const int j0 = lane * 4;            // 4 features per lane (2 packed pairs)
    float* my_attr = attr_s + e0 * NUM_RBF;   // 8x64 slice
    float* my_h    = h_s    + e0 * NF;        // 8x128 slice

    const float4 b1v = *reinterpret_cast<const float4*>(&b1s[j0]);
    const float4 b2v = *reinterpret_cast<const float4*>(&b2s[j0]);

    const int n_tiles = N_EDGES / TILE_E;   // 12500 exact
    for (int t = blockIdx.x; t < n_tiles; t += gridDim.x) {
        const int base = t * TILE_E + e0;   // first edge of this warp's group

        // --- per-warp edge metadata + attr staging ---
        if (lane < 8) {
            int e = base + lane;
            srcs[e0 + lane] = clamp_idx(edge_index[e]);
            dsts[e0 + lane] = clamp_idx(edge_index[N_EDGES + e]);
            float w = edge_weight[e];
            float c = 0.5f * (__cosf(w * (PI_F / CUTOFF)) + 1.0f);
            Cs[e0 + lane] = (w < CUTOFF) ? c : 0.0f;
        }
        // 8 rows x 64 floats = 128 float4 -> 4 per lane, coalesced
        {
            const float4* gsrc = reinterpret_cast<const float4*>(edge_attr + base * NUM_RBF);
            float4* ssrc = reinterpret_cast<float4*>(my_attr);
            #pragma unroll
            for (int i = 0; i < 4; i++)
                ssrc[lane + 32 * i] = gsrc[lane + 32 * i];
        }
        __syncwarp();

        // ---- phase 1: h = silu(attr @ W1 + b1), packed f32x2 ----
        unsigned long long acc0[8], acc1[8];
        #pragma unroll
        for (int i = 0; i < 8; i++) { acc0[i] = 0ull; acc1[i] = 0ull; }

        #pragma unroll 4
        for (int k4 = 0; k4 < NUM_RBF / 4; k4++) {
            float4 a4[8];
            #pragma unroll
            for (int i = 0; i < 8; i++)
                a4[i] = *reinterpret_cast<const float4*>(&my_attr[i * NUM_RBF + k4 * 4]);
            #pragma unroll
            for (int kk = 0; kk < 4; kk++) {
                const int k = k4 * 4 + kk;
                unsigned long long w01, w23;
                lds_v2u64(&W1s[k * NF + j0], w01, w23);
                #pragma unroll
                for (int i = 0; i < 8; i++) {
                    float a = (kk == 0) ? a4[i].x : (kk == 1) ? a4[i].y
                             : (kk == 2) ? a4[i].z : a4[i].w;
                    unsigned long long ap = pack_rep2(a);
                    fma2(acc0[i], ap, w01);
                    fma2(acc1[i], ap, w23);
                }
            }
        }
        #pragma unroll
        for (int i = 0; i < 8; i++) {
            float p0, p1, p2, p3;
            unpack2(acc0[i], p0, p1);
            unpack2(acc1[i], p2, p3);
            float4 h4;
            h4.x = silu_f(p0 + b1v.x);
            h4.y = silu_f(p1 + b1v.y);
            h4.z = silu_f(p2 + b1v.z);
            h4.w = silu_f(p3 + b1v.w);
            *reinterpret_cast<float4*>(&my_h[i * NF + j0]) = h4;
        }
        __syncwarp();

        // ---- phase 2: W = (h @ W2 + b2) * C ; gather * W ; scatter ----
        #pragma unroll
        for (int i = 0; i < 8; i++) { acc0[i] = 0ull; acc1[i] = 0ull; }

        #pragma unroll 4
        for (int k4 = 0; k4 < NF / 4; k4++) {
            float4 a4[8];
            #pragma unroll
            for (int i = 0; i < 8; i++)
                a4[i] = *reinterpret_cast<const float4*>(&my_h[i * NF + k4 * 4]);
            #pragma unroll
            for (int kk = 0; kk < 4; kk++) {
                const int k = k4 * 4 + kk;
                unsigned long long w01, w23;
                lds_v2u64(&W2s[k * NF + j0], w01, w23);
                #pragma unroll
                for (int i = 0; i < 8; i++) {
                    float a = (kk == 0) ? a4[i].x : (kk == 1) ? a4[i].y
                             : (kk == 2) ? a4[i].z : a4[i].w;
                    unsigned long long ap = pack_rep2(a);
                    fma2(acc0[i], ap, w01);
                    fma2(acc1[i], ap, w23);
                }
            }
        }

        #pragma unroll
        for (int i = 0; i < 8; i++) {
            const float c = Cs[e0 + i];
            const int s = srcs[e0 + i];
            const int d = dsts[e0 + i];
            float p0, p1, p2, p3;
            unpack2(acc0[i], p0, p1);
            unpack2(acc1[i], p2, p3);
            float4 xf4 = *reinterpret_cast<const float4*>(&g_xf[s * NF + j0]);
            float* dst = &g_agg[d * NF + j0];
            atomicAdd(dst + 0, (p0 + b2v.x) * c * xf4.x);
            atomicAdd(dst + 1, (p1 + b2v.y) * c * xf4.y);
            atomicAdd(dst + 2, (p2 + b2v.z) * c * xf4.z);
            atomicAdd(dst + 3, (p3 + b2v.w) * c * xf4.w);
        }
        __syncwarp();   // protect per-warp smem slices before next tile
    }
}

// ---------------------------------------------------------------------------
// Kernel 5: node tail
// ---------------------------------------------------------------------------
__global__ void node_kernel(const float* __restrict__ lin2_w,
                            const float* __restrict__ lin2_b,
                            const float* __restrict__ lin_w,
                            const float* __restrict__ lin_b,
                            float* __restrict__ out) {
    extern __shared__ float sm[];
    float* L2s = sm;             // 128*128
    float* Ls  = L2s + 16384;    // 128*128
    float* b2s = Ls + 16384;     // 128
    float* bs  = b2s + 128;      // 128
    float* a_s = bs + 128;       // 64*128
    float* t_s = a_s + 8192;     // 64*128

    const int tid = threadIdx.x;
    for (int i = tid; i < 16384 / 4; i += 512) {
        reinterpret_cast<float4*>(L2s)[i] =
            reinterpret_cast<const float4*>(lin2_w)[i];
        reinterpret_cast<float4*>(Ls)[i] =
            reinterpret_cast<const float4*>(lin_w)[i];
    }
    if (tid < 128) { b2s[tid] = lin2_b[tid]; bs[tid] = lin_b[tid]; }
    __syncthreads();

    const int j0 = (tid & 31) * 4;
    const int n0 = (tid >> 5) * 4;

    const int n_tiles = (N_NODES + 63) / 64;
    for (int t = blockIdx.x; t < n_tiles; t += gridDim.x) {
        const int base = t * 64;

        for (int i = tid; i < 64 * 32; i += 512) {
            int r  = i >> 5;
            int cg = i & 31;
            int n  = base + r;
            float4 v = make_float4(0.f, 0.f, 0.f, 0.f);
            if (n < N_NODES) {
                v = *reinterpret_cast<const float4*>(&g_agg[n * NF + cg * 4]);
                float inv = 1.0f / fmaxf(g_cnt[n], 1.0f);
                v.x *= inv; v.y *= inv; v.z *= inv; v.w *= inv;
            }
            *reinterpret_cast<float4*>(&a_s[r * NF + cg * 4]) = v;
        }
        __syncthreads();

        float4 acc[4];
        #pragma unroll
        for (int i = 0; i < 4; i++) acc[i] = make_float4(0.f, 0.f, 0.f, 0.f);
        #pragma unroll 8
        for (int k = 0; k < NF; k++) {
            float4 w4 = *reinterpret_cast<const float4*>(&L2s[k * HIDDEN + j0]);
            #pragma unroll
            for (int i = 0; i < 4; i++) {
                float a = a_s[(n0 + i) * NF + k];
                acc[i].x += a * w4.x; acc[i].y += a * w4.y;
                acc[i].z += a * w4.z; acc[i].w += a * w4.w;
            }
        }
        {
            float4 bv = *reinterpret_cast<const float4*>(&b2s[j0]);
            #pragma unroll
            for (int i = 0; i < 4; i++) {
                float4 h4;
                h4.x = silu_f(acc[i].x + bv.x);
                h4.y = silu_f(acc[i].y + bv.y);
                h4.z = silu_f(acc[i].z + bv.z);
                h4.w = silu_f(acc[i].w + bv.w);
                *reinterpret_cast<float4*>(&t_s[(n0 + i) * HIDDEN + j0]) = h4;
            }
        }
        __syncthreads();

        #pragma unroll
        for (int i = 0; i < 4; i++) acc[i] = make_float4(0.f, 0.f, 0.f, 0.f);
        #pragma unroll 8
        for (int k = 0; k < HIDDEN; k++) {
            float4 w4 = *reinterpret_cast<const float4*>(&Ls[k * HIDDEN + j0]);
            #pragma unroll
            for (int i = 0; i < 4; i++) {
                float a = t_s[(n0 + i) * HIDDEN + k];
                acc[i].x += a * w4.x; acc[i].y += a * w4.y;
                acc[i].z += a * w4.z; acc[i].w += a * w4.w;
            }
        }
        {
            float4 bv = *reinterpret_cast<const float4*>(&bs[j0]);
            #pragma unroll
            for (int i = 0; i < 4; i++) {
                int n = base + n0 + i;
                if (n < N_NODES) {
                    float4 o;
                    o.x = acc[i].x + bv.x; o.y = acc[i].y + bv.y;
                    o.z = acc[i].z + bv.z; o.w = acc[i].w + bv.w;
                    *reinterpret_cast<float4*>(&out[n * HIDDEN + j0]) = o;
                }
            }
        }
        __syncthreads();
    }
}

// ---------------------------------------------------------------------------
// launch
// ---------------------------------------------------------------------------
extern "C" void kernel_launch(void* const* d_in, const int* in_sizes, int n_in,
                              void* d_out, int out_size) {
    const float* x   = (const float*)d_in[0];
    const int*   ei  = (const int*)d_in[1];      // int32 (JAX x64 disabled)
    const float* ew  = (const float*)d_in[2];
    const float* ea  = (const float*)d_in[3];
    const float* w1  = (const float*)d_in[4];
    const float* b1  = (const float*)d_in[5];
    const float* w2  = (const float*)d_in[6];
    const float* b2  = (const float*)d_in[7];
    const float* l1w = (const float*)d_in[8];
    const float* l2w = (const float*)d_in[9];
    const float* l2b = (const float*)d_in[10];
    const float* lw  = (const float*)d_in[11];
    const float* lb  = (const float*)d_in[12];
    float* out = (float*)d_out;

    const int smem_xf   = (16384 + 4096) * 4;
    const int smem_edge = 49792 * 4;
    const int smem_node = 49408 * 4;
    cudaFuncSetAttribute(xf_kernel,   cudaFuncAttributeMaxDynamicSharedMemorySize, smem_xf);
    cudaFuncSetAttribute(edge_kernel, cudaFuncAttributeMaxDynamicSharedMemorySize, smem_edge);
    cudaFuncSetAttribute(node_kernel, cudaFuncAttributeMaxDynamicSharedMemorySize, smem_node);

    zero_kernel<<<1024, 256>>>();
    cnt_kernel<<<2048, 256>>>(ei);
    xf_kernel<<<296, 256, smem_xf>>>(x, l1w);
    edge_kernel<<<148, 512, smem_edge>>>(ei, ew, ea, w1, b1, w2, b2);
    node_kernel<<<148, 512, smem_node>>>(l2w, l2b, lw, lb, out);
}

// round 6
// speedup vs baseline: 1.5881x; 1.0158x over previous
#include <cuda_runtime.h>
#include <math.h>
#include <stdint.h>

#define N_NODES   100000
#define N_EDGES   1600000
#define HIDDEN    128
#define NUM_RBF   64
#define NF        128
#define CUTOFF    5.0f
#define PI_F      3.14159265358979323846f

// ---------------------------------------------------------------------------
// Scratch
// ---------------------------------------------------------------------------
__device__ __align__(16) float g_xf [N_NODES * NF];
__device__ __align__(16) float g_agg[N_NODES * NF];
__device__ float g_cnt[N_NODES];

__device__ __forceinline__ float silu_f(float v) {
    return v / (1.0f + __expf(-v));
}

__device__ __forceinline__ int clamp_idx(int v) {
    v = v < 0 ? 0 : v;
    return v >= N_NODES ? N_NODES - 1 : v;
}

// ---- f32x2 packed-FMA helpers (Blackwell; FFMA2 only reachable via PTX) ----
__device__ __forceinline__ unsigned long long pack_rep2(float a) {
    unsigned long long r;
    asm("mov.b64 %0, {%1, %1};" : "=l"(r) : "f"(a));
    return r;
}
__device__ __forceinline__ void fma2(unsigned long long& d,
                                     unsigned long long a,
                                     unsigned long long b) {
    asm("fma.rn.f32x2 %0, %1, %2, %0;" : "+l"(d) : "l"(a), "l"(b));
}
__device__ __forceinline__ void unpack2(unsigned long long v, float& lo, float& hi) {
    asm("mov.b64 {%0, %1}, %2;" : "=f"(lo), "=f"(hi) : "l"(v));
}
__device__ __forceinline__ void lds_v2u64(const float* p,
                                          unsigned long long& w01,
                                          unsigned long long& w23) {
    uint32_t addr = (uint32_t)__cvta_generic_to_shared(p);
    asm("ld.shared.v2.u64 {%0, %1}, [%2];" : "=l"(w01), "=l"(w23) : "r"(addr));
}

// Vectorized fire-and-forget global reduction (16B aligned addresses).
__device__ __forceinline__ void red_add_v4(float* addr, float a, float b,
                                           float c, float d) {
    asm volatile("red.global.add.v4.f32 [%0], {%1, %2, %3, %4};"
                 :: "l"(addr), "f"(a), "f"(b), "f"(c), "f"(d)
                 : "memory");
}

// ---------------------------------------------------------------------------
// Kernel 1: zero agg + cnt
// ---------------------------------------------------------------------------
__global__ void zero_kernel() {
    int idx = blockIdx.x * blockDim.x + threadIdx.x;
    int stride = gridDim.x * blockDim.x;
    float4* agg4 = reinterpret_cast<float4*>(g_agg);
    const int n4 = N_NODES * (NF / 4);
    float4 z = make_float4(0.f, 0.f, 0.f, 0.f);
    for (int i = idx; i < n4; i += stride) agg4[i] = z;
    for (int i = idx; i < N_NODES; i += stride) g_cnt[i] = 0.f;
}

// ---------------------------------------------------------------------------
// Kernel 2: in-degree counts
// ---------------------------------------------------------------------------
__global__ void cnt_kernel(const int* __restrict__ edge_index) {
    int idx = blockIdx.x * blockDim.x + threadIdx.x;
    int stride = gridDim.x * blockDim.x;
    for (int e = idx; e < N_EDGES; e += stride) {
        int d = clamp_idx(edge_index[N_EDGES + e]);
        atomicAdd(&g_cnt[d], 1.0f);
    }
}

// ---------------------------------------------------------------------------
// Kernel 3: xf = x @ lin1_w
// ---------------------------------------------------------------------------
__global__ void xf_kernel(const float* __restrict__ x,
                          const float* __restrict__ lin1_w) {
    extern __shared__ float sm[];
    float* ws = sm;            // 128*128
    float* xs = ws + 16384;    // 32*128

    const int tid = threadIdx.x;
    for (int i = tid; i < 16384 / 4; i += 256)
        reinterpret_cast<float4*>(ws)[i] =
            reinterpret_cast<const float4*>(lin1_w)[i];
    __syncthreads();

    const int j0 = (tid & 31) * 4;
    const int n0 = (tid >> 5) * 4;

    const int n_tiles = N_NODES / 32;
    for (int t = blockIdx.x; t < n_tiles; t += gridDim.x) {
        const int base = t * 32;
        for (int i = tid; i < 32 * 32; i += 256)
            reinterpret_cast<float4*>(xs)[i] =
                reinterpret_cast<const float4*>(x + base * HIDDEN)[i];
        __syncthreads();

        float4 acc[4];
        #pragma unroll
        for (int i = 0; i < 4; i++) acc[i] = make_float4(0.f, 0.f, 0.f, 0.f);

        #pragma unroll 8
        for (int k = 0; k < HIDDEN; k++) {
            float4 w4 = *reinterpret_cast<const float4*>(&ws[k * NF + j0]);
            #pragma unroll
            for (int i = 0; i < 4; i++) {
                float a = xs[(n0 + i) * HIDDEN + k];
                acc[i].x += a * w4.x; acc[i].y += a * w4.y;
                acc[i].z += a * w4.z; acc[i].w += a * w4.w;
            }
        }
        #pragma unroll
        for (int i = 0; i < 4; i++)
            *reinterpret_cast<float4*>(&g_xf[(base + n0 + i) * NF + j0]) = acc[i];
        __syncthreads();
    }
}

// ---------------------------------------------------------------------------
// Kernel 4: fused edge kernel, f32x2 packed math, warp-autonomous,
//           vectorized red.global.add.v4 scatter
// ---------------------------------------------------------------------------
#define TILE_E 128   // 16 warps * 8 edges
__global__ __launch_bounds__(512, 1)
void edge_kernel(const int* __restrict__ edge_index,
                 const float* __restrict__ edge_weight,
                 const float* __restrict__ edge_attr,
                 const float* __restrict__ mlp_w1,
                 const float* __restrict__ mlp_b1,
                 const float* __restrict__ mlp_w2,
                 const float* __restrict__ mlp_b2) {
    extern __shared__ float sm[];
    float* W1s    = sm;                 // 64*128   =  8192
    float* W2s    = W1s + 8192;         // 128*128  = 16384
    float* b1s    = W2s + 16384;        // 128
    float* b2s    = b1s + 128;          // 128
    float* attr_s = b2s + 128;          // 128*64   =  8192
    float* h_s    = attr_s + 8192;      // 128*128  = 16384
    float* Cs     = h_s + 16384;        // 128
    int*   srcs   = (int*)(Cs + 128);   // 128
    int*   dsts   = srcs + 128;         // 128

    const int tid  = threadIdx.x;
    const int lane = tid & 31;
    const int wrp  = tid >> 5;          // 0..15
    const int e0   = wrp * 8;

    for (int i = tid; i < 8192 / 4; i += 512)
        reinterpret_cast<float4*>(W1s)[i] =
            reinterpret_cast<const float4*>(mlp_w1)[i];
    for (int i = tid; i < 16384 / 4; i += 512)
        reinterpret_cast<float4*>(W2s)[i] =
            reinterpret_cast<const float4*>(mlp_w2)[i];
    if (tid < 128) { b1s[tid] = mlp_b1[tid]; b2s[tid] = mlp_b2[tid]; }
    __syncthreads();

    const int j0 = lane * 4;
    float* my_attr = attr_s + e0 * NUM_RBF;
    float* my_h    = h_s    + e0 * NF;

    const float4 b1v = *reinterpret_cast<const float4*>(&b1s[j0]);
    const float4 b2v = *reinterpret_cast<const float4*>(&b2s[j0]);

    const int n_tiles = N_EDGES / TILE_E;   // 12500 exact
    for (int t = blockIdx.x; t < n_tiles; t += gridDim.x) {
        const int base = t * TILE_E + e0;

        if (lane < 8) {
            int e = base + lane;
            srcs[e0 + lane] = clamp_idx(edge_index[e]);
            dsts[e0 + lane] = clamp_idx(edge_index[N_EDGES + e]);
            float w = edge_weight[e];
            float c = 0.5f * (__cosf(w * (PI_F / CUTOFF)) + 1.0f);
            Cs[e0 + lane] = (w < CUTOFF) ? c : 0.0f;
        }
        {
            const float4* gsrc = reinterpret_cast<const float4*>(edge_attr + base * NUM_RBF);
            float4* ssrc = reinterpret_cast<float4*>(my_attr);
            #pragma unroll
            for (int i = 0; i < 4; i++)
                ssrc[lane + 32 * i] = gsrc[lane + 32 * i];
        }
        __syncwarp();

        // ---- phase 1: h = silu(attr @ W1 + b1), packed f32x2 ----
        unsigned long long acc0[8], acc1[8];
        #pragma unroll
        for (int i = 0; i < 8; i++) { acc0[i] = 0ull; acc1[i] = 0ull; }

        #pragma unroll 4
        for (int k4 = 0; k4 < NUM_RBF / 4; k4++) {
            float4 a4[8];
            #pragma unroll
            for (int i = 0; i < 8; i++)
                a4[i] = *reinterpret_cast<const float4*>(&my_attr[i * NUM_RBF + k4 * 4]);
            #pragma unroll
            for (int kk = 0; kk < 4; kk++) {
                const int k = k4 * 4 + kk;
                unsigned long long w01, w23;
                lds_v2u64(&W1s[k * NF + j0], w01, w23);
                #pragma unroll
                for (int i = 0; i < 8; i++) {
                    float a = (kk == 0) ? a4[i].x : (kk == 1) ? a4[i].y
                             : (kk == 2) ? a4[i].z : a4[i].w;
                    unsigned long long ap = pack_rep2(a);
                    fma2(acc0[i], ap, w01);
                    fma2(acc1[i], ap, w23);
                }
            }
        }
        #pragma unroll
        for (int i = 0; i < 8; i++) {
            float p0, p1, p2, p3;
            unpack2(acc0[i], p0, p1);
            unpack2(acc1[i], p2, p3);
            float4 h4;
            h4.x = silu_f(p0 + b1v.x);
            h4.y = silu_f(p1 + b1v.y);
            h4.z = silu_f(p2 + b1v.z);
            h4.w = silu_f(p3 + b1v.w);
            *reinterpret_cast<float4*>(&my_h[i * NF + j0]) = h4;
        }
        __syncwarp();

        // ---- phase 2: W = (h @ W2 + b2) * C ; gather * W ; scatter ----
        #pragma unroll
        for (int i = 0; i < 8; i++) { acc0[i] = 0ull; acc1[i] = 0ull; }

        #pragma unroll 4
        for (int k4 = 0; k4 < NF / 4; k4++) {
            float4 a4[8];
            #pragma unroll
            for (int i = 0; i < 8; i++)
                a4[i] = *reinterpret_cast<const float4*>(&my_h[i * NF + k4 * 4]);
            #pragma unroll
            for (int kk = 0; kk < 4; kk++) {
                const int k = k4 * 4 + kk;
                unsigned long long w01, w23;
                lds_v2u64(&W2s[k * NF + j0], w01, w23);
                #pragma unroll
                for (int i = 0; i < 8; i++) {
                    float a = (kk == 0) ? a4[i].x : (kk == 1) ? a4[i].y
                             : (kk == 2) ? a4[i].z : a4[i].w;
                    unsigned long long ap = pack_rep2(a);
                    fma2(acc0[i], ap, w01);
                    fma2(acc1[i], ap, w23);
                }
            }
        }

        #pragma unroll
        for (int i = 0; i < 8; i++) {
            const float c = Cs[e0 + i];
            const int s = srcs[e0 + i];
            const int d = dsts[e0 + i];
            float p0, p1, p2, p3;
            unpack2(acc0[i], p0, p1);
            unpack2(acc1[i], p2, p3);
            float4 xf4 = *reinterpret_cast<const float4*>(&g_xf[s * NF + j0]);
            red_add_v4(&g_agg[d * NF + j0],
                       (p0 + b2v.x) * c * xf4.x,
                       (p1 + b2v.y) * c * xf4.y,
                       (p2 + b2v.z) * c * xf4.z,
                       (p3 + b2v.w) * c * xf4.w);
        }
        __syncwarp();
    }
}

// ---------------------------------------------------------------------------
// Kernel 5: node tail
// ---------------------------------------------------------------------------
__global__ void node_kernel(const float* __restrict__ lin2_w,
                            const float* __restrict__ lin2_b,
                            const float* __restrict__ lin_w,
                            const float* __restrict__ lin_b,
                            float* __restrict__ out) {
    extern __shared__ float sm[];
    float* L2s = sm;             // 128*128
    float* Ls  = L2s + 16384;    // 128*128
    float* b2s = Ls + 16384;     // 128
    float* bs  = b2s + 128;      // 128
    float* a_s = bs + 128;       // 64*128
    float* t_s = a_s + 8192;     // 64*128

    const int tid = threadIdx.x;
    for (int i = tid; i < 16384 / 4; i += 512) {
        reinterpret_cast<float4*>(L2s)[i] =
            reinterpret_cast<const float4*>(lin2_w)[i];
        reinterpret_cast<float4*>(Ls)[i] =
            reinterpret_cast<const float4*>(lin_w)[i];
    }
    if (tid < 128) { b2s[tid] = lin2_b[tid]; bs[tid] = lin_b[tid]; }
    __syncthreads();

    const int j0 = (tid & 31) * 4;
    const int n0 = (tid >> 5) * 4;

    const int n_tiles = (N_NODES + 63) / 64;
    for (int t = blockIdx.x; t < n_tiles; t += gridDim.x) {
        const int base = t * 64;

        for (int i = tid; i < 64 * 32; i += 512) {
            int r  = i >> 5;
            int cg = i & 31;
            int n  = base + r;
            float4 v = make_float4(0.f, 0.f, 0.f, 0.f);
            if (n < N_NODES) {
                v = *reinterpret_cast<const float4*>(&g_agg[n * NF + cg * 4]);
                float inv = 1.0f / fmaxf(g_cnt[n], 1.0f);
                v.x *= inv; v.y *= inv; v.z *= inv; v.w *= inv;
            }
            *reinterpret_cast<float4*>(&a_s[r * NF + cg * 4]) = v;
        }
        __syncthreads();

        float4 acc[4];
        #pragma unroll
        for (int i = 0; i < 4; i++) acc[i] = make_float4(0.f, 0.f, 0.f, 0.f);
        #pragma unroll 8
        for (int k = 0; k < NF; k++) {
            float4 w4 = *reinterpret_cast<const float4*>(&L2s[k * HIDDEN + j0]);
            #pragma unroll
            for (int i = 0; i < 4; i++) {
                float a = a_s[(n0 + i) * NF + k];
                acc[i].x += a * w4.x; acc[i].y += a * w4.y;
                acc[i].z += a * w4.z; acc[i].w += a * w4.w;
            }
        }
        {
            float4 bv = *reinterpret_cast<const float4*>(&b2s[j0]);
            #pragma unroll
            for (int i = 0; i < 4; i++) {
                float4 h4;
                h4.x = silu_f(acc[i].x + bv.x);
                h4.y = silu_f(acc[i].y + bv.y);
                h4.z = silu_f(acc[i].z + bv.z);
                h4.w = silu_f(acc[i].w + bv.w);
                *reinterpret_cast<float4*>(&t_s[(n0 + i) * HIDDEN + j0]) = h4;
            }
        }
        __syncthreads();

        #pragma unroll
        for (int i = 0; i < 4; i++) acc[i] = make_float4(0.f, 0.f, 0.f, 0.f);
        #pragma unroll 8
        for (int k = 0; k < HIDDEN; k++) {
            float4 w4 = *reinterpret_cast<const float4*>(&Ls[k * HIDDEN + j0]);
            #pragma unroll
            for (int i = 0; i < 4; i++) {
                float a = t_s[(n0 + i) * HIDDEN + k];
                acc[i].x += a * w4.x; acc[i].y += a * w4.y;
                acc[i].z += a * w4.z; acc[i].w += a * w4.w;
            }
        }
        {
            float4 bv = *reinterpret_cast<const float4*>(&bs[j0]);
            #pragma unroll
            for (int i = 0; i < 4; i++) {
                int n = base + n0 + i;
                if (n < N_NODES) {
                    float4 o;
                    o.x = acc[i].x + bv.x; o.y = acc[i].y + bv.y;
                    o.z = acc[i].z + bv.z; o.w = acc[i].w + bv.w;
                    *reinterpret_cast<float4*>(&out[n * HIDDEN + j0]) = o;
                }
            }
        }
        __syncthreads();
    }
}

// ---------------------------------------------------------------------------
// launch
// ---------------------------------------------------------------------------
extern "C" void kernel_launch(void* const* d_in, const int* in_sizes, int n_in,
                              void* d_out, int out_size) {
    const float* x   = (const float*)d_in[0];
    const int*   ei  = (const int*)d_in[1];      // int32 (JAX x64 disabled)
    const float* ew  = (const float*)d_in[2];
    const float* ea  = (const float*)d_in[3];
    const float* w1  = (const float*)d_in[4];
    const float* b1  = (const float*)d_in[5];
    const float* w2  = (const float*)d_in[6];
    const float* b2  = (const float*)d_in[7];
    const float* l1w = (const float*)d_in[8];
    const float* l2w = (const float*)d_in[9];
    const float* l2b = (const float*)d_in[10];
    const float* lw  = (const float*)d_in[11];
    const float* lb  = (const float*)d_in[12];
    float* out = (float*)d_out;

    const int smem_xf   = (16384 + 4096) * 4;
    const int smem_edge = 49792 * 4;
    const int smem_node = 49408 * 4;
    cudaFuncSetAttribute(xf_kernel,   cudaFuncAttributeMaxDynamicSharedMemorySize, smem_xf);
    cudaFuncSetAttribute(edge_kernel, cudaFuncAttributeMaxDynamicSharedMemorySize, smem_edge);
    cudaFuncSetAttribute(node_kernel, cudaFuncAttributeMaxDynamicSharedMemorySize, smem_node);

    zero_kernel<<<1024, 256>>>();
    cnt_kernel<<<2048, 256>>>(ei);
    xf_kernel<<<296, 256, smem_xf>>>(x, l1w);
    edge_kernel<<<148, 512, smem_edge>>>(ei, ew, ea, w1, b1, w2, b2);
    node_kernel<<<148, 512, smem_node>>>(l2w, l2b, lw, lb, out);
}